// round 10
// baseline (speedup 1.0000x reference)
#include <cuda_runtime.h>
#include <math_constants.h>

#define NF 8
#define NQ 300
#define HH 96
#define WW 96
#define HW (HH*WW)        // 9216
#define FHW (NF*HW)       // 73728
#define ALPHA_C 0.25f
#define EPSV 1e-8f
#define LN2F 0.69314718056f

// transposed meta: g_metaT[bf][c*96 + row] = {tmask bits, vpad bits}
__device__ __align__(16) uint2 g_metaT[16][3*HH];
__device__ unsigned g_done;

typedef unsigned long long u64;
__device__ __forceinline__ u64 pk(float lo, float hi) {
    u64 r; asm("mov.b64 %0,{%1,%2};" : "=l"(r) : "f"(lo), "f"(hi)); return r;
}
__device__ __forceinline__ void upk(u64 v, float& lo, float& hi) {
    asm("mov.b64 {%0,%1},%2;" : "=f"(lo), "=f"(hi) : "l"(v));
}
__device__ __forceinline__ u64 fma2(u64 a, u64 b, u64 c) {
    u64 d; asm("fma.rn.f32x2 %0,%1,%2,%3;" : "=l"(d) : "l"(a), "l"(b), "l"(c)); return d;
}
__device__ __forceinline__ u64 add2(u64 a, u64 b) {
    u64 d; asm("add.rn.f32x2 %0,%1,%2;" : "=l"(d) : "l"(a), "l"(b)); return d;
}
__device__ __forceinline__ u64 mul2(u64 a, u64 b) {
    u64 d; asm("mul.rn.f32x2 %0,%1,%2;" : "=l"(d) : "l"(a), "l"(b)); return d;
}

__device__ __forceinline__ float tanh_hw(float x) {
    float y; asm("tanh.approx.f32 %0, %1;" : "=f"(y) : "f"(x)); return y;
}
__device__ __forceinline__ float sigmoid_fast(float x) {
    float a = fabsf(x);
    float u = __expf(-a);
    float r = __fdividef(1.0f, 1.0f + u);
    return (x >= 0.0f) ? r : u * r;
}
__device__ __forceinline__ float warp_sum(float v) {
    #pragma unroll
    for (int o = 16; o; o >>= 1) v += __shfl_xor_sync(0xffffffff, v, o);
    return v;
}
__device__ __forceinline__ float warp_max(float v) {
    #pragma unroll
    for (int o = 16; o; o >>= 1) v = fmaxf(v, __shfl_xor_sync(0xffffffff, v, o));
    return v;
}

// ---------------------------------------------------------------------------
// Prep: ballots only, transposed meta layout. grid = 192 blocks, 128 threads.
// ---------------------------------------------------------------------------
__global__ __launch_bounds__(128) void prep_kernel(
    const float* __restrict__ tmask, const unsigned char* __restrict__ vpad)
{
    if (blockIdx.x == 0 && threadIdx.x == 0) g_done = 0u;
    int bf = blockIdx.x / 12;       // 0..15
    int rg = blockIdx.x % 12;       // row group of 8
    int b = bf >> 3;
    int tid = threadIdx.x;
    int wp = tid >> 5, lane = tid & 31;
    const float* base = tmask + (size_t)bf * HW;
    const unsigned char* vb = vpad + (size_t)b * HW;

    #pragma unroll
    for (int rr = 0; rr < 2; ++rr) {
        int row = rg * 8 + wp * 2 + rr;
        const float* rp = base + row * WW;
        const unsigned char* vr = vb + row * WW;
        float v0 = rp[lane], v1 = rp[32 + lane], v2 = rp[64 + lane];
        unsigned char q0 = vr[lane], q1 = vr[32 + lane], q2 = vr[64 + lane];
        unsigned t0 = __ballot_sync(0xffffffff, v0 != 0.0f);
        unsigned t1 = __ballot_sync(0xffffffff, v1 != 0.0f);
        unsigned t2 = __ballot_sync(0xffffffff, v2 != 0.0f);
        unsigned p0 = __ballot_sync(0xffffffff, q0 != 0);
        unsigned p1 = __ballot_sync(0xffffffff, q1 != 0);
        unsigned p2 = __ballot_sync(0xffffffff, q2 != 0);
        if (lane == 0) {
            g_metaT[bf][0 * HH + row] = make_uint2(t0, p0);
            g_metaT[bf][1 * HH + row] = make_uint2(t1, p1);
            g_metaT[bf][2 * HH + row] = make_uint2(t2, p2);
        }
    }
}

// ---------------------------------------------------------------------------
// Cost: one block per (b,q). 192 threads = 6 warps; warp owns 16 rows (8 pairs).
// Packed f32x2 focal math. Last block performs argmin + tail writes.
// ---------------------------------------------------------------------------
__global__ __launch_bounds__(192, 5) void cost_kernel(
    const float* __restrict__ logits,
    const float* __restrict__ boxes,
    const float* __restrict__ masks,
    const float* __restrict__ tbox,
    const int*   __restrict__ tvalid,
    float* __restrict__ C, int out_size)
{
    int blk = blockIdx.x;
    int b = blk / NQ, q = blk % NQ;
    int tid = threadIdx.x;
    int warp = tid >> 5, lane = tid & 31;
    unsigned bitm = 1u << lane;

    __shared__ float rowFinal[NF * HH];           // 3 KB
    __shared__ float colAll[NF * 3 * 192];        // 18 KB
    __shared__ unsigned orAll[NF * 3 * 6];
    __shared__ float red[6][10];
    __shared__ bool isLast;

    const u64 C05   = pk(0.5f, 0.5f);
    const u64 CM05  = pk(-0.5f, -0.5f);
    const u64 C075  = pk(0.75f, 0.75f);
    const u64 CLN2  = pk(LN2F, LN2F);
    const u64 CLN2N = pk(-LN2F, -LN2F);
    const u64 CM1   = pk(-1.0f, -1.0f);

    u64 facc2 = pk(0.f, 0.f), nacc2 = pk(0.f, 0.f), sacc2 = pk(0.f, 0.f);

    for (int f = 0; f < NF; ++f) {
        const float* mb = masks + (size_t)((b * NF + f) * NQ + q) * HW + lane;
        const uint2* mt = g_metaT[b * NF + f];
        float c0 = -CUDART_INF_F, c1 = -CUDART_INF_F, c2 = -CUDART_INF_F;
        unsigned o0 = 0u, o1 = 0u, o2 = 0u;
        #pragma unroll 2
        for (int pr = 0; pr < 8; ++pr) {
            int row = warp * 16 + pr * 2;       // even
            // meta for rows (row, row+1), per chunk: one LDG.128 each
            uint4 mw0 = *reinterpret_cast<const uint4*>(&mt[0 * HH + row]);
            uint4 mw1 = *reinterpret_cast<const uint4*>(&mt[1 * HH + row]);
            uint4 mw2 = *reinterpret_cast<const uint4*>(&mt[2 * HH + row]);
            const float* rpa = mb + row * WW;
            const float* rpb = rpa + WW;
            float xa0 = rpa[0], xa1 = rpa[32], xa2 = rpa[64];
            float xb0 = rpb[0], xb1 = rpb[32], xb2 = rpb[64];
            if (mw0.y & bitm) xa0 = 0.0f;
            if (mw1.y & bitm) xa1 = 0.0f;
            if (mw2.y & bitm) xa2 = 0.0f;
            if (mw0.w & bitm) xb0 = 0.0f;
            if (mw1.w & bitm) xb1 = 0.0f;
            if (mw2.w & bitm) xb2 = 0.0f;
            o0 |= mw0.x | mw0.z;
            o1 |= mw1.x | mw1.z;
            o2 |= mw2.x | mw2.z;

            #pragma unroll
            for (int c = 0; c < 3; ++c) {
                float xa = (c == 0) ? xa0 : (c == 1) ? xa1 : xa2;
                float xb = (c == 0) ? xb0 : (c == 1) ? xb1 : xb2;
                unsigned ta = (c == 0) ? mw0.x : (c == 1) ? mw1.x : mw2.x;
                unsigned tb = (c == 0) ? mw0.z : (c == 1) ? mw1.z : mw2.z;
                float tfa = (ta & bitm) ? 1.0f : 0.0f;
                float tfb = (tb & bitm) ? 1.0f : 0.0f;
                float tha = tanh_hw(0.5f * xa);
                float thb = tanh_hw(0.5f * xb);
                float la = __log2f(1.0f + fabsf(tha));
                float lb = __log2f(1.0f + fabsf(thb));
                float ma = fmaxf(xa, 0.0f);
                float mbv = fmaxf(xb, 0.0f);

                u64 x2  = pk(xa, xb);
                u64 th2 = pk(tha, thb);
                u64 lg2 = pk(la, lb);
                u64 m2  = pk(ma, mbv);
                u64 tf2 = pk(tfa, tfb);

                u64 mpl2 = add2(m2, CLN2);               // max(x,0)+ln2
                u64 ce2a = fma2(lg2, CLN2N, mpl2);       // - ln2*log2(1+|th|)
                u64 xt2  = mul2(x2, tf2);
                u64 ce2  = fma2(xt2, CM1, ce2a);         // - x*t
                u64 p2   = fma2(th2, C05, C05);          // sigmoid
                u64 nth2 = mul2(th2, CM1);
                u64 omp2 = fma2(tf2, nth2, p2);          // 1 - p_t
                u64 at2  = fma2(tf2, CM05, C075);        // alpha_t
                u64 t1   = mul2(at2, ce2);
                u64 oo2  = mul2(omp2, omp2);
                facc2 = fma2(t1, oo2, facc2);
                sacc2 = add2(sacc2, th2);
                nacc2 = fma2(p2, tf2, nacc2);
            }
            c0 = fmaxf(c0, fmaxf(xa0, xb0));
            c1 = fmaxf(c1, fmaxf(xa1, xb1));
            c2 = fmaxf(c2, fmaxf(xa2, xb2));
            float rma = warp_max(fmaxf(fmaxf(xa0, xa1), xa2));
            float rmb = warp_max(fmaxf(fmaxf(xb0, xb1), xb2));
            if (lane == 0) {
                rowFinal[f * HH + row] = rma;
                rowFinal[f * HH + row + 1] = rmb;
            }
        }
        colAll[((f * 3 + 0) * 6 + warp) * 32 + lane] = c0;
        colAll[((f * 3 + 1) * 6 + warp) * 32 + lane] = c1;
        colAll[((f * 3 + 2) * 6 + warp) * 32 + lane] = c2;
        if (lane == 0) {
            orAll[(f * 3 + 0) * 6 + warp] = o0;
            orAll[(f * 3 + 1) * 6 + warp] = o1;
            orAll[(f * 3 + 2) * 6 + warp] = o2;
        }
    }
    __syncthreads();

    float faccA, faccB, naccA, naccB, saccA, saccB;
    upk(facc2, faccA, faccB);
    upk(nacc2, naccA, naccB);
    upk(sacc2, saccA, saccB);
    float facc = faccA + faccB, nacc = naccA + naccB, sacc = saccA + saccB;

    // projection partials + target stats from bits
    float sx = 0, nx = 0, sy = 0, ny = 0, tsum = 0, txs = 0, tys = 0;
    #pragma unroll
    for (int j = tid; j < NF * HH; j += 192) {
        int f = j / 96, jj = j % 96;
        const uint2* mt = g_metaT[b * NF + f];
        uint2 w0 = mt[0 * HH + jj], w1 = mt[1 * HH + jj], w2 = mt[2 * HH + jj];
        tsum += (float)(__popc(w0.x) + __popc(w1.x) + __popc(w2.x));
        float tgx = ((w0.x | w1.x | w2.x) != 0u) ? 1.0f : 0.0f;
        float px = sigmoid_fast(rowFinal[j]);
        sx += px; nx += px * tgx; txs += tgx;

        int c = jj >> 5, l = jj & 31;
        const float* cp = &colAll[((f * 3 + c) * 6) * 32 + l];
        const unsigned* op = &orAll[(f * 3 + c) * 6];
        float m = cp[0];
        unsigned ow = op[0];
        #pragma unroll
        for (int wp = 1; wp < 6; ++wp) { m = fmaxf(m, cp[wp * 32]); ow |= op[wp]; }
        float tgy = ((ow >> l) & 1u) ? 1.0f : 0.0f;
        float py = sigmoid_fast(m);
        sy += py; ny += py * tgy; tys += tgy;
    }

    float v0 = warp_sum(facc), v1 = warp_sum(nacc), v2 = warp_sum(sacc);
    float v3 = warp_sum(sx),   v4 = warp_sum(nx);
    float v5 = warp_sum(sy),   v6 = warp_sum(ny);
    float v7 = warp_sum(tsum), v8 = warp_sum(txs), v9 = warp_sum(tys);
    if (lane == 0) {
        red[warp][0] = v0; red[warp][1] = v1; red[warp][2] = v2;
        red[warp][3] = v3; red[warp][4] = v4; red[warp][5] = v5; red[warp][6] = v6;
        red[warp][7] = v7; red[warp][8] = v8; red[warp][9] = v9;
    }
    __syncthreads();

    if (tid == 0) {
        float A[10];
        #pragma unroll
        for (int i = 0; i < 10; ++i) {
            float t = 0;
            #pragma unroll
            for (int w = 0; w < 6; ++w) t += red[w][i];
            A[i] = t;
        }
        float naccr = A[1];                        // sum_{t} p (computed directly)
        float saccr = 0.5f * ((float)FHW + A[2]);  // sum p from th-sums
        float cost_mask = A[0] / (float)FHW;
        float cost_dice = -((2.0f * naccr + 1.0f) / (saccr + A[7] + 1.0f));
        float dx = (2.0f * A[4] + 1.0f) / (A[3] + A[8] + 1.0f);
        float dy = (2.0f * A[6] + 1.0f) / (A[5] + A[9] + 1.0f);
        float cost_proj = -0.5f * (dy + dx);

        float cls = 0, wsum = 0, bbox = 0, giou = 0;
        #pragma unroll
        for (int f = 0; f < NF; ++f) {
            float lg = logits[(b * NF + f) * NQ + q];
            float p = sigmoid_fast(lg);
            float neg = (1.0f - ALPHA_C) * p * p * (-__logf(1.0f - p + EPSV));
            float pos = ALPHA_C * (1.0f - p) * (1.0f - p) * (-__logf(p + EPSV));
            float wv = (tvalid[b * NF + f] != 0) ? 1.0f : 0.0f;
            cls += (pos - neg) * wv; wsum += wv;

            const float* bx = boxes + (size_t)((b * NF + f) * NQ + q) * 4;
            const float* tx = tbox + (size_t)(b * NF + f) * 4;
            bbox += fabsf(bx[0]-tx[0]) + fabsf(bx[1]-tx[1]) + fabsf(bx[2]-tx[2]) + fabsf(bx[3]-tx[3]);

            float sx0 = bx[0]-0.5f*bx[2], sy0 = bx[1]-0.5f*bx[3];
            float sx1 = bx[0]+0.5f*bx[2], sy1 = bx[1]+0.5f*bx[3];
            float tx0 = tx[0]-0.5f*tx[2], ty0 = tx[1]-0.5f*tx[3];
            float tx1 = tx[0]+0.5f*tx[2], ty1 = tx[1]+0.5f*tx[3];
            float a1 = (sx1-sx0)*(sy1-sy0);
            float a2 = (tx1-tx0)*(ty1-ty0);
            float iw = fmaxf(fminf(sx1,tx1) - fmaxf(sx0,tx0), 0.0f);
            float ih = fmaxf(fminf(sy1,ty1) - fmaxf(sy0,ty0), 0.0f);
            float inter = iw * ih;
            float uni = a1 + a2 - inter;
            float iou = inter / uni;
            float cw = fmaxf(fmaxf(sx1,tx1) - fminf(sx0,tx0), 0.0f);
            float ch = fmaxf(fmaxf(sy1,ty1) - fminf(sy0,ty0), 0.0f);
            float ac = cw * ch;
            giou += -(iou - (ac - uni) / ac);
        }
        C[b * NQ + q] = cls / wsum + bbox * (1.0f / NF) + giou * (1.0f / NF)
                      + cost_mask + cost_dice + cost_proj;
    }

    // ---- last block performs argmin + tail writes ----
    if (tid == 0) {
        __threadfence();
        unsigned v = atomicAdd(&g_done, 1u);
        isLast = (v == 2 * NQ - 1);
    }
    __syncthreads();
    if (!isLast) return;
    __threadfence();

    for (int bb = 0; bb < 2; ++bb) {
        float best = CUDART_INF_F; int bi = NQ;
        for (int qq = tid; qq < NQ; qq += 192) {
            float vv = C[bb * NQ + qq];
            if (vv < best || (vv == best && qq < bi)) { best = vv; bi = qq; }
        }
        #pragma unroll
        for (int o = 16; o; o >>= 1) {
            float ov = __shfl_down_sync(0xffffffff, best, o);
            int   oi = __shfl_down_sync(0xffffffff, bi,   o);
            if (ov < best || (ov == best && oi < bi)) { best = ov; bi = oi; }
        }
        __shared__ float sv[6]; __shared__ int si[6];
        if (lane == 0) { sv[warp] = best; si[warp] = bi; }
        __syncthreads();
        if (tid == 0) {
            for (int i = 1; i < 6; ++i) {
                if (sv[i] < best || (sv[i] == best && si[i] < bi)) { best = sv[i]; bi = si[i]; }
            }
            if (out_size >= 608) {
                long long* op = (long long*)(C + 600);
                op[bb] = (long long)bi;
                op[2 + bb] = 0ll;
                if (bb == 0) for (int i = 608; i < out_size; ++i) C[i] = 0.0f;
            } else if (out_size >= 604) {
                C[600 + bb] = (float)bi;
                C[602 + bb] = 0.0f;
                if (bb == 0) for (int i = 604; i < out_size; ++i) C[i] = 0.0f;
            } else {
                if (bb == 0) for (int i = 600; i < out_size; ++i) C[i] = 0.0f;
            }
        }
        __syncthreads();
    }
}

extern "C" void kernel_launch(void* const* d_in, const int* in_sizes, int n_in,
                              void* d_out, int out_size) {
    const float* logits = (const float*)d_in[0];
    const float* boxes  = (const float*)d_in[1];
    const float* masks  = (const float*)d_in[2];
    const float* tmask  = (const float*)d_in[3];
    const float* tbox   = (const float*)d_in[4];
    const int*   tvalid = (const int*)d_in[5];
    const unsigned char* vpad = (const unsigned char*)d_in[6];
    float* out = (float*)d_out;

    prep_kernel<<<192, 128>>>(tmask, vpad);
    cost_kernel<<<2 * NQ, 192>>>(logits, boxes, masks, tbox, tvalid, out, out_size);
}

// round 11
// speedup vs baseline: 1.1056x; 1.1056x over previous
#include <cuda_runtime.h>
#include <math_constants.h>

#define NF 8
#define NQ 300
#define HH 96
#define WW 96
#define HW (HH*WW)        // 9216
#define FHW (NF*HW)       // 73728
#define ALPHA_C 0.25f
#define EPSV 1e-8f
#define LN2F 0.69314718056f

// transposed meta: g_metaT[bf][c*96 + row] = {tmask bits, vpad bits}
__device__ __align__(16) uint2 g_metaT[16][3*HH];
__device__ float g_scr[2*NQ][2][10];
__device__ int g_qdone[2*NQ];
__device__ unsigned g_done;

__device__ __forceinline__ float tanh_hw(float x) {
    float y; asm("tanh.approx.f32 %0, %1;" : "=f"(y) : "f"(x)); return y;
}
__device__ __forceinline__ float sigmoid_fast(float x) {
    float a = fabsf(x);
    float u = __expf(-a);
    float r = __fdividef(1.0f, 1.0f + u);
    return (x >= 0.0f) ? r : u * r;
}
__device__ __forceinline__ float warp_sum(float v) {
    #pragma unroll
    for (int o = 16; o; o >>= 1) v += __shfl_xor_sync(0xffffffff, v, o);
    return v;
}
__device__ __forceinline__ float warp_max(float v) {
    #pragma unroll
    for (int o = 16; o; o >>= 1) v = fmaxf(v, __shfl_xor_sync(0xffffffff, v, o));
    return v;
}

// ---------------------------------------------------------------------------
// Prep: ballots + counter resets. grid = 192 blocks, 128 threads.
// ---------------------------------------------------------------------------
__global__ __launch_bounds__(128) void prep_kernel(
    const float* __restrict__ tmask, const unsigned char* __restrict__ vpad)
{
    if (blockIdx.x == 0) {
        if (threadIdx.x == 0) g_done = 0u;
        for (int i = threadIdx.x; i < 2 * NQ; i += 128) g_qdone[i] = 0;
    }
    int bf = blockIdx.x / 12;       // 0..15
    int rg = blockIdx.x % 12;       // row group of 8
    int b = bf >> 3;
    int tid = threadIdx.x;
    int wp = tid >> 5, lane = tid & 31;
    const float* base = tmask + (size_t)bf * HW;
    const unsigned char* vb = vpad + (size_t)b * HW;

    #pragma unroll
    for (int rr = 0; rr < 2; ++rr) {
        int row = rg * 8 + wp * 2 + rr;
        const float* rp = base + row * WW;
        const unsigned char* vr = vb + row * WW;
        float v0 = rp[lane], v1 = rp[32 + lane], v2 = rp[64 + lane];
        unsigned char q0 = vr[lane], q1 = vr[32 + lane], q2 = vr[64 + lane];
        unsigned t0 = __ballot_sync(0xffffffff, v0 != 0.0f);
        unsigned t1 = __ballot_sync(0xffffffff, v1 != 0.0f);
        unsigned t2 = __ballot_sync(0xffffffff, v2 != 0.0f);
        unsigned p0 = __ballot_sync(0xffffffff, q0 != 0);
        unsigned p1 = __ballot_sync(0xffffffff, q1 != 0);
        unsigned p2 = __ballot_sync(0xffffffff, q2 != 0);
        if (lane == 0) {
            g_metaT[bf][0 * HH + row] = make_uint2(t0, p0);
            g_metaT[bf][1 * HH + row] = make_uint2(t1, p1);
            g_metaT[bf][2 * HH + row] = make_uint2(t2, p2);
        }
    }
}

// ---------------------------------------------------------------------------
// Cost: one block per (b,q,half); 4 frames each. 192 threads = 6 warps.
// Warp owns 16 rows of each of its 4 frames. Second finisher per query runs
// the epilogue; global last block runs argmin.
// ---------------------------------------------------------------------------
__global__ __launch_bounds__(192, 6) void cost_kernel(
    const float* __restrict__ logits,
    const float* __restrict__ boxes,
    const float* __restrict__ masks,
    const float* __restrict__ tbox,
    const int*   __restrict__ tvalid,
    float* __restrict__ C, int out_size)
{
    int blk = blockIdx.x;               // 0..1199
    int bq = blk >> 1, half = blk & 1;
    int b = bq / NQ, q = bq % NQ;
    int f0 = half * 4;
    int tid = threadIdx.x;
    int warp = tid >> 5, lane = tid & 31;
    unsigned bitm = 1u << lane;

    __shared__ float rowFinal[4 * HH];            // 1.5 KB
    __shared__ float colAll[4 * 3 * 192];         // 9 KB
    __shared__ unsigned orAll[4 * 3 * 6];
    __shared__ float red[6][10];
    __shared__ int myTurn;

    float facc = 0.0f, nacc = 0.0f, sacc = 0.0f;

    for (int f = 0; f < 4; ++f) {
        const float* mb = masks + (size_t)((b * NF + f0 + f) * NQ + q) * HW + lane;
        const uint2* mt = g_metaT[b * NF + f0 + f];
        float c0 = -CUDART_INF_F, c1 = -CUDART_INF_F, c2 = -CUDART_INF_F;
        unsigned o0 = 0u, o1 = 0u, o2 = 0u;
        #pragma unroll 2
        for (int pr = 0; pr < 8; ++pr) {
            int row = warp * 16 + pr * 2;
            uint4 mw0 = *reinterpret_cast<const uint4*>(&mt[0 * HH + row]);
            uint4 mw1 = *reinterpret_cast<const uint4*>(&mt[1 * HH + row]);
            uint4 mw2 = *reinterpret_cast<const uint4*>(&mt[2 * HH + row]);
            const float* rpa = mb + row * WW;
            const float* rpb = rpa + WW;
            float xa0 = rpa[0], xa1 = rpa[32], xa2 = rpa[64];
            float xb0 = rpb[0], xb1 = rpb[32], xb2 = rpb[64];
            if (mw0.y & bitm) xa0 = 0.0f;
            if (mw1.y & bitm) xa1 = 0.0f;
            if (mw2.y & bitm) xa2 = 0.0f;
            if (mw0.w & bitm) xb0 = 0.0f;
            if (mw1.w & bitm) xb1 = 0.0f;
            if (mw2.w & bitm) xb2 = 0.0f;
            o0 |= mw0.x | mw0.z;
            o1 |= mw1.x | mw1.z;
            o2 |= mw2.x | mw2.z;

            #pragma unroll
            for (int c = 0; c < 3; ++c) {
                float xa = (c == 0) ? xa0 : (c == 1) ? xa1 : xa2;
                float xb = (c == 0) ? xb0 : (c == 1) ? xb1 : xb2;
                unsigned twa = (c == 0) ? mw0.x : (c == 1) ? mw1.x : mw2.x;
                unsigned twb = (c == 0) ? mw0.z : (c == 1) ? mw1.z : mw2.z;
                // element A
                {
                    bool tb = (twa & bitm) != 0u;
                    float th = tanh_hw(0.5f * xa);
                    float lg2v = __log2f(1.0f + fabsf(th));
                    float xs = tb ? -xa : xa;
                    float m = fmaxf(xs, 0.0f);
                    float ce = fmaf(-LN2F, lg2v, m + LN2F);
                    float u = tb ? th : -th;
                    float omu = 1.0f - u;
                    float at4 = tb ? 0.0625f : 0.1875f;
                    facc = fmaf(ce * omu * omu, at4, facc);
                    sacc += th;
                    if (tb) nacc += th;
                }
                // element B
                {
                    bool tb = (twb & bitm) != 0u;
                    float th = tanh_hw(0.5f * xb);
                    float lg2v = __log2f(1.0f + fabsf(th));
                    float xs = tb ? -xb : xb;
                    float m = fmaxf(xs, 0.0f);
                    float ce = fmaf(-LN2F, lg2v, m + LN2F);
                    float u = tb ? th : -th;
                    float omu = 1.0f - u;
                    float at4 = tb ? 0.0625f : 0.1875f;
                    facc = fmaf(ce * omu * omu, at4, facc);
                    sacc += th;
                    if (tb) nacc += th;
                }
            }
            c0 = fmaxf(c0, fmaxf(xa0, xb0));
            c1 = fmaxf(c1, fmaxf(xa1, xb1));
            c2 = fmaxf(c2, fmaxf(xa2, xb2));
            float rma = warp_max(fmaxf(fmaxf(xa0, xa1), xa2));
            float rmb = warp_max(fmaxf(fmaxf(xb0, xb1), xb2));
            if (lane == 0) {
                rowFinal[f * HH + row] = rma;
                rowFinal[f * HH + row + 1] = rmb;
            }
        }
        colAll[((f * 3 + 0) * 6 + warp) * 32 + lane] = c0;
        colAll[((f * 3 + 1) * 6 + warp) * 32 + lane] = c1;
        colAll[((f * 3 + 2) * 6 + warp) * 32 + lane] = c2;
        if (lane == 0) {
            orAll[(f * 3 + 0) * 6 + warp] = o0;
            orAll[(f * 3 + 1) * 6 + warp] = o1;
            orAll[(f * 3 + 2) * 6 + warp] = o2;
        }
    }
    __syncthreads();

    // projection partials + target stats: 384 rows + 384 cols, 2 each/thread
    float sx = 0, nx = 0, sy = 0, ny = 0, tsum = 0, txs = 0, tys = 0;
    #pragma unroll
    for (int j = tid; j < 4 * HH; j += 192) {
        int f = j / 96, jj = j % 96;
        const uint2* mt = g_metaT[b * NF + f0 + f];
        uint2 w0 = mt[0 * HH + jj], w1 = mt[1 * HH + jj], w2 = mt[2 * HH + jj];
        tsum += (float)(__popc(w0.x) + __popc(w1.x) + __popc(w2.x));
        float tgx = ((w0.x | w1.x | w2.x) != 0u) ? 1.0f : 0.0f;
        float px = sigmoid_fast(rowFinal[j]);
        sx += px; nx += px * tgx; txs += tgx;

        int c = jj >> 5, l = jj & 31;
        const float* cp = &colAll[((f * 3 + c) * 6) * 32 + l];
        const unsigned* op = &orAll[(f * 3 + c) * 6];
        float m = cp[0];
        unsigned ow = op[0];
        #pragma unroll
        for (int wp = 1; wp < 6; ++wp) { m = fmaxf(m, cp[wp * 32]); ow |= op[wp]; }
        float tgy = ((ow >> l) & 1u) ? 1.0f : 0.0f;
        float py = sigmoid_fast(m);
        sy += py; ny += py * tgy; tys += tgy;
    }

    float v0 = warp_sum(facc), v1 = warp_sum(nacc), v2 = warp_sum(sacc);
    float v3 = warp_sum(sx),   v4 = warp_sum(nx);
    float v5 = warp_sum(sy),   v6 = warp_sum(ny);
    float v7 = warp_sum(tsum), v8 = warp_sum(txs), v9 = warp_sum(tys);
    if (lane == 0) {
        red[warp][0] = v0; red[warp][1] = v1; red[warp][2] = v2;
        red[warp][3] = v3; red[warp][4] = v4; red[warp][5] = v5; red[warp][6] = v6;
        red[warp][7] = v7; red[warp][8] = v8; red[warp][9] = v9;
    }
    __syncthreads();
    if (warp == 0 && lane < 10) {
        float t = 0;
        #pragma unroll
        for (int w = 0; w < 6; ++w) t += red[w][lane];
        g_scr[bq][half][lane] = t;
    }
    __syncthreads();

    // per-query: second finisher does the epilogue
    if (tid == 0) {
        __threadfence();
        myTurn = atomicAdd(&g_qdone[bq], 1);
    }
    __syncthreads();
    if (myTurn == 1 && tid == 0) {
        __threadfence();
        float A[10];
        #pragma unroll
        for (int i = 0; i < 10; ++i) A[i] = g_scr[bq][0][i] + g_scr[bq][1][i];

        float naccr = 0.5f * (A[7] + A[1]);
        float saccr = 0.5f * ((float)FHW + A[2]);
        float cost_mask = A[0] / (float)FHW;
        float cost_dice = -((2.0f * naccr + 1.0f) / (saccr + A[7] + 1.0f));
        float dx = (2.0f * A[4] + 1.0f) / (A[3] + A[8] + 1.0f);
        float dy = (2.0f * A[6] + 1.0f) / (A[5] + A[9] + 1.0f);
        float cost_proj = -0.5f * (dy + dx);

        float cls = 0, wsum = 0, bbox = 0, giou = 0;
        #pragma unroll
        for (int f = 0; f < NF; ++f) {
            float lg = logits[(b * NF + f) * NQ + q];
            float p = sigmoid_fast(lg);
            float neg = (1.0f - ALPHA_C) * p * p * (-__logf(1.0f - p + EPSV));
            float pos = ALPHA_C * (1.0f - p) * (1.0f - p) * (-__logf(p + EPSV));
            float wv = (tvalid[b * NF + f] != 0) ? 1.0f : 0.0f;
            cls += (pos - neg) * wv; wsum += wv;

            const float* bx = boxes + (size_t)((b * NF + f) * NQ + q) * 4;
            const float* tx = tbox + (size_t)(b * NF + f) * 4;
            bbox += fabsf(bx[0]-tx[0]) + fabsf(bx[1]-tx[1]) + fabsf(bx[2]-tx[2]) + fabsf(bx[3]-tx[3]);

            float sx0 = bx[0]-0.5f*bx[2], sy0 = bx[1]-0.5f*bx[3];
            float sx1 = bx[0]+0.5f*bx[2], sy1 = bx[1]+0.5f*bx[3];
            float tx0 = tx[0]-0.5f*tx[2], ty0 = tx[1]-0.5f*tx[3];
            float tx1 = tx[0]+0.5f*tx[2], ty1 = tx[1]+0.5f*tx[3];
            float a1 = (sx1-sx0)*(sy1-sy0);
            float a2 = (tx1-tx0)*(ty1-ty0);
            float iw = fmaxf(fminf(sx1,tx1) - fmaxf(sx0,tx0), 0.0f);
            float ih = fmaxf(fminf(sy1,ty1) - fmaxf(sy0,ty0), 0.0f);
            float inter = iw * ih;
            float uni = a1 + a2 - inter;
            float iou = inter / uni;
            float cw = fmaxf(fmaxf(sx1,tx1) - fminf(sx0,tx0), 0.0f);
            float ch = fmaxf(fmaxf(sy1,ty1) - fminf(sy0,ty0), 0.0f);
            float ac = cw * ch;
            giou += -(iou - (ac - uni) / ac);
        }
        C[bq] = cls / wsum + bbox * (1.0f / NF) + giou * (1.0f / NF)
              + cost_mask + cost_dice + cost_proj;
    }

    // global last block does argmin
    __shared__ bool isLast;
    if (tid == 0) {
        isLast = false;
        if (myTurn == 1) {
            __threadfence();
            unsigned v = atomicAdd(&g_done, 1u);
            isLast = (v == 2 * NQ - 1);
        }
    }
    __syncthreads();
    if (!isLast) return;
    __threadfence();

    for (int bb = 0; bb < 2; ++bb) {
        float best = CUDART_INF_F; int bi = NQ;
        for (int qq = tid; qq < NQ; qq += 192) {
            float vv = C[bb * NQ + qq];
            if (vv < best || (vv == best && qq < bi)) { best = vv; bi = qq; }
        }
        #pragma unroll
        for (int o = 16; o; o >>= 1) {
            float ov = __shfl_down_sync(0xffffffff, best, o);
            int   oi = __shfl_down_sync(0xffffffff, bi,   o);
            if (ov < best || (ov == best && oi < bi)) { best = ov; bi = oi; }
        }
        __shared__ float sv[6]; __shared__ int si[6];
        if (lane == 0) { sv[warp] = best; si[warp] = bi; }
        __syncthreads();
        if (tid == 0) {
            for (int i = 1; i < 6; ++i) {
                if (sv[i] < best || (sv[i] == best && si[i] < bi)) { best = sv[i]; bi = si[i]; }
            }
            if (out_size >= 608) {
                long long* op = (long long*)(C + 600);
                op[bb] = (long long)bi;
                op[2 + bb] = 0ll;
                if (bb == 0) for (int i = 608; i < out_size; ++i) C[i] = 0.0f;
            } else if (out_size >= 604) {
                C[600 + bb] = (float)bi;
                C[602 + bb] = 0.0f;
                if (bb == 0) for (int i = 604; i < out_size; ++i) C[i] = 0.0f;
            } else {
                if (bb == 0) for (int i = 600; i < out_size; ++i) C[i] = 0.0f;
            }
        }
        __syncthreads();
    }
}

extern "C" void kernel_launch(void* const* d_in, const int* in_sizes, int n_in,
                              void* d_out, int out_size) {
    const float* logits = (const float*)d_in[0];
    const float* boxes  = (const float*)d_in[1];
    const float* masks  = (const float*)d_in[2];
    const float* tmask  = (const float*)d_in[3];
    const float* tbox   = (const float*)d_in[4];
    const int*   tvalid = (const int*)d_in[5];
    const unsigned char* vpad = (const unsigned char*)d_in[6];
    float* out = (float*)d_out;

    prep_kernel<<<192, 128>>>(tmask, vpad);
    cost_kernel<<<4 * NQ, 192>>>(logits, boxes, masks, tbox, tvalid, out, out_size);
}

// round 12
// speedup vs baseline: 1.1587x; 1.0480x over previous
#include <cuda_runtime.h>
#include <math_constants.h>

#define NF 8
#define NQ 300
#define HH 96
#define WW 96
#define HW (HH*WW)        // 9216
#define FHW (NF*HW)       // 73728
#define ALPHA_C 0.25f
#define EPSV 1e-8f
#define LN2F 0.69314718056f

// transposed meta: g_metaT[bf][c*96 + row] = {tmask bits, vpad bits}
__device__ __align__(16) uint2 g_metaT[16][3*HH];
__device__ unsigned g_done;

__device__ __forceinline__ float tanh_hw(float x) {
    float y; asm("tanh.approx.f32 %0, %1;" : "=f"(y) : "f"(x)); return y;
}
__device__ __forceinline__ float sigmoid_fast(float x) {
    float a = fabsf(x);
    float u = __expf(-a);
    float r = __fdividef(1.0f, 1.0f + u);
    return (x >= 0.0f) ? r : u * r;
}
__device__ __forceinline__ float warp_sum(float v) {
    #pragma unroll
    for (int o = 16; o; o >>= 1) v += __shfl_xor_sync(0xffffffff, v, o);
    return v;
}
__device__ __forceinline__ float warp_max(float v) {
    #pragma unroll
    for (int o = 16; o; o >>= 1) v = fmaxf(v, __shfl_xor_sync(0xffffffff, v, o));
    return v;
}
__device__ __forceinline__ void cp16(unsigned dst, const void* src) {
    asm volatile("cp.async.cg.shared.global [%0], [%1], 16;" :: "r"(dst), "l"(src));
}

// ---------------------------------------------------------------------------
// Prep: ballots + counter reset. grid = 192 blocks, 128 threads.
// ---------------------------------------------------------------------------
__global__ __launch_bounds__(128) void prep_kernel(
    const float* __restrict__ tmask, const unsigned char* __restrict__ vpad)
{
    if (blockIdx.x == 0 && threadIdx.x == 0) g_done = 0u;
    int bf = blockIdx.x / 12;
    int rg = blockIdx.x % 12;
    int b = bf >> 3;
    int tid = threadIdx.x;
    int wp = tid >> 5, lane = tid & 31;
    const float* base = tmask + (size_t)bf * HW;
    const unsigned char* vb = vpad + (size_t)b * HW;

    #pragma unroll
    for (int rr = 0; rr < 2; ++rr) {
        int row = rg * 8 + wp * 2 + rr;
        const float* rp = base + row * WW;
        const unsigned char* vr = vb + row * WW;
        float v0 = rp[lane], v1 = rp[32 + lane], v2 = rp[64 + lane];
        unsigned char q0 = vr[lane], q1 = vr[32 + lane], q2 = vr[64 + lane];
        unsigned t0 = __ballot_sync(0xffffffff, v0 != 0.0f);
        unsigned t1 = __ballot_sync(0xffffffff, v1 != 0.0f);
        unsigned t2 = __ballot_sync(0xffffffff, v2 != 0.0f);
        unsigned p0 = __ballot_sync(0xffffffff, q0 != 0);
        unsigned p1 = __ballot_sync(0xffffffff, q1 != 0);
        unsigned p2 = __ballot_sync(0xffffffff, q2 != 0);
        if (lane == 0) {
            g_metaT[bf][0 * HH + row] = make_uint2(t0, p0);
            g_metaT[bf][1 * HH + row] = make_uint2(t1, p1);
            g_metaT[bf][2 * HH + row] = make_uint2(t2, p2);
        }
    }
}

// ---------------------------------------------------------------------------
// Cost: one block per (b,q). 192 threads = 6 warps; warp owns 16 rows/frame.
// Per-warp cp.async double-buffered pipeline over 32 chunks of 4 rows.
// ---------------------------------------------------------------------------
__global__ __launch_bounds__(192, 4) void cost_kernel(
    const float* __restrict__ logits,
    const float* __restrict__ boxes,
    const float* __restrict__ masks,
    const float* __restrict__ tbox,
    const int*   __restrict__ tvalid,
    float* __restrict__ C, int out_size)
{
    int blk = blockIdx.x;
    int b = blk / NQ, q = blk % NQ;
    int tid = threadIdx.x;
    int warp = tid >> 5, lane = tid & 31;
    unsigned bitm = 1u << lane;

    __shared__ float stage[6][2][384];            // 18 KB, per-warp double buffer
    __shared__ float rowFinal[NF * HH];           // 3 KB
    __shared__ float colAll[NF * 3 * 192];        // 18 KB
    __shared__ unsigned orAll[NF * 3 * 6];
    __shared__ float red[6][10];
    __shared__ bool isLast;

    unsigned sbase = (unsigned)__cvta_generic_to_shared(&stage[warp][0][0]);
    size_t qoff = ((size_t)(b * NF) * NQ + q) * HW;   // frame 0 of this (b,q)

    // issue chunk c into buffer c&1: frame c>>2, rows warp*16 + (c&3)*4 .. +4
    auto issue = [&](int c) {
        int f = c >> 2, cc = c & 3;
        const float* src = masks + qoff + (size_t)f * NQ * HW
                         + (warp * 16 + cc * 4) * WW + lane * 4;
        unsigned dst = sbase + (unsigned)(c & 1) * 1536u + lane * 16u;
        #pragma unroll
        for (int u = 0; u < 3; ++u)
            cp16(dst + u * 512u, src + u * 128);
        asm volatile("cp.async.commit_group;");
    };

    float facc = 0.0f, nacc = 0.0f, sacc = 0.0f;
    float c0 = -CUDART_INF_F, c1 = -CUDART_INF_F, c2 = -CUDART_INF_F;
    unsigned o0 = 0u, o1 = 0u, o2 = 0u;

    issue(0);
    for (int c = 0; c < 32; ++c) {
        if (c + 1 < 32) issue(c + 1);
        if (c + 1 < 32) asm volatile("cp.async.wait_group 1;");
        else            asm volatile("cp.async.wait_group 0;");
        __syncwarp();

        int f = c >> 2, cc = c & 3, buf = c & 1;
        const float* sm = &stage[warp][buf][0];
        const uint2* mt = g_metaT[b * NF + f];
        #pragma unroll
        for (int pr = 0; pr < 2; ++pr) {
            int row = warp * 16 + cc * 4 + pr * 2;
            int lr = pr * 2;
            uint4 mw0 = *reinterpret_cast<const uint4*>(&mt[0 * HH + row]);
            uint4 mw1 = *reinterpret_cast<const uint4*>(&mt[1 * HH + row]);
            uint4 mw2 = *reinterpret_cast<const uint4*>(&mt[2 * HH + row]);
            float xa0 = sm[lr * 96 + lane];
            float xa1 = sm[lr * 96 + 32 + lane];
            float xa2 = sm[lr * 96 + 64 + lane];
            float xb0 = sm[lr * 96 + 96 + lane];
            float xb1 = sm[lr * 96 + 128 + lane];
            float xb2 = sm[lr * 96 + 160 + lane];
            if (mw0.y & bitm) xa0 = 0.0f;
            if (mw1.y & bitm) xa1 = 0.0f;
            if (mw2.y & bitm) xa2 = 0.0f;
            if (mw0.w & bitm) xb0 = 0.0f;
            if (mw1.w & bitm) xb1 = 0.0f;
            if (mw2.w & bitm) xb2 = 0.0f;
            o0 |= mw0.x | mw0.z;
            o1 |= mw1.x | mw1.z;
            o2 |= mw2.x | mw2.z;

            #pragma unroll
            for (int cch = 0; cch < 3; ++cch) {
                float xa = (cch == 0) ? xa0 : (cch == 1) ? xa1 : xa2;
                float xb = (cch == 0) ? xb0 : (cch == 1) ? xb1 : xb2;
                unsigned twa = (cch == 0) ? mw0.x : (cch == 1) ? mw1.x : mw2.x;
                unsigned twb = (cch == 0) ? mw0.z : (cch == 1) ? mw1.z : mw2.z;
                {
                    bool tb = (twa & bitm) != 0u;
                    float th = tanh_hw(0.5f * xa);
                    float lg2v = __log2f(1.0f + fabsf(th));
                    float xs = tb ? -xa : xa;
                    float m = fmaxf(xs, 0.0f);
                    float ce = fmaf(-LN2F, lg2v, m + LN2F);
                    float u = tb ? th : -th;
                    float omu = 1.0f - u;
                    float at4 = tb ? 0.0625f : 0.1875f;
                    facc = fmaf(ce * omu * omu, at4, facc);
                    sacc += th;
                    if (tb) nacc += th;
                }
                {
                    bool tb = (twb & bitm) != 0u;
                    float th = tanh_hw(0.5f * xb);
                    float lg2v = __log2f(1.0f + fabsf(th));
                    float xs = tb ? -xb : xb;
                    float m = fmaxf(xs, 0.0f);
                    float ce = fmaf(-LN2F, lg2v, m + LN2F);
                    float u = tb ? th : -th;
                    float omu = 1.0f - u;
                    float at4 = tb ? 0.0625f : 0.1875f;
                    facc = fmaf(ce * omu * omu, at4, facc);
                    sacc += th;
                    if (tb) nacc += th;
                }
            }
            c0 = fmaxf(c0, fmaxf(xa0, xb0));
            c1 = fmaxf(c1, fmaxf(xa1, xb1));
            c2 = fmaxf(c2, fmaxf(xa2, xb2));
            float rma = warp_max(fmaxf(fmaxf(xa0, xa1), xa2));
            float rmb = warp_max(fmaxf(fmaxf(xb0, xb1), xb2));
            if (lane == 0) {
                rowFinal[f * HH + row] = rma;
                rowFinal[f * HH + row + 1] = rmb;
            }
        }
        if (cc == 3) {      // end of frame f
            colAll[((f * 3 + 0) * 6 + warp) * 32 + lane] = c0;
            colAll[((f * 3 + 1) * 6 + warp) * 32 + lane] = c1;
            colAll[((f * 3 + 2) * 6 + warp) * 32 + lane] = c2;
            if (lane == 0) {
                orAll[(f * 3 + 0) * 6 + warp] = o0;
                orAll[(f * 3 + 1) * 6 + warp] = o1;
                orAll[(f * 3 + 2) * 6 + warp] = o2;
            }
            c0 = c1 = c2 = -CUDART_INF_F;
            o0 = o1 = o2 = 0u;
        }
        __syncwarp();       // protect buffer reuse
    }
    __syncthreads();

    // projection partials + target stats from bits
    float sx = 0, nx = 0, sy = 0, ny = 0, tsum = 0, txs = 0, tys = 0;
    #pragma unroll
    for (int j = tid; j < NF * HH; j += 192) {
        int f = j / 96, jj = j % 96;
        const uint2* mt = g_metaT[b * NF + f];
        uint2 w0 = mt[0 * HH + jj], w1 = mt[1 * HH + jj], w2 = mt[2 * HH + jj];
        tsum += (float)(__popc(w0.x) + __popc(w1.x) + __popc(w2.x));
        float tgx = ((w0.x | w1.x | w2.x) != 0u) ? 1.0f : 0.0f;
        float px = sigmoid_fast(rowFinal[j]);
        sx += px; nx += px * tgx; txs += tgx;

        int cc = jj >> 5, l = jj & 31;
        const float* cp = &colAll[((f * 3 + cc) * 6) * 32 + l];
        const unsigned* op = &orAll[(f * 3 + cc) * 6];
        float m = cp[0];
        unsigned ow = op[0];
        #pragma unroll
        for (int wp = 1; wp < 6; ++wp) { m = fmaxf(m, cp[wp * 32]); ow |= op[wp]; }
        float tgy = ((ow >> l) & 1u) ? 1.0f : 0.0f;
        float py = sigmoid_fast(m);
        sy += py; ny += py * tgy; tys += tgy;
    }

    float v0 = warp_sum(facc), v1 = warp_sum(nacc), v2 = warp_sum(sacc);
    float v3 = warp_sum(sx),   v4 = warp_sum(nx);
    float v5 = warp_sum(sy),   v6 = warp_sum(ny);
    float v7 = warp_sum(tsum), v8 = warp_sum(txs), v9 = warp_sum(tys);
    if (lane == 0) {
        red[warp][0] = v0; red[warp][1] = v1; red[warp][2] = v2;
        red[warp][3] = v3; red[warp][4] = v4; red[warp][5] = v5; red[warp][6] = v6;
        red[warp][7] = v7; red[warp][8] = v8; red[warp][9] = v9;
    }
    __syncthreads();

    if (tid == 0) {
        float A[10];
        #pragma unroll
        for (int i = 0; i < 10; ++i) {
            float t = 0;
            #pragma unroll
            for (int w = 0; w < 6; ++w) t += red[w][i];
            A[i] = t;
        }
        float naccr = 0.5f * (A[7] + A[1]);
        float saccr = 0.5f * ((float)FHW + A[2]);
        float cost_mask = A[0] / (float)FHW;
        float cost_dice = -((2.0f * naccr + 1.0f) / (saccr + A[7] + 1.0f));
        float dx = (2.0f * A[4] + 1.0f) / (A[3] + A[8] + 1.0f);
        float dy = (2.0f * A[6] + 1.0f) / (A[5] + A[9] + 1.0f);
        float cost_proj = -0.5f * (dy + dx);

        float cls = 0, wsum = 0, bbox = 0, giou = 0;
        #pragma unroll
        for (int f = 0; f < NF; ++f) {
            float lg = logits[(b * NF + f) * NQ + q];
            float p = sigmoid_fast(lg);
            float neg = (1.0f - ALPHA_C) * p * p * (-__logf(1.0f - p + EPSV));
            float pos = ALPHA_C * (1.0f - p) * (1.0f - p) * (-__logf(p + EPSV));
            float wv = (tvalid[b * NF + f] != 0) ? 1.0f : 0.0f;
            cls += (pos - neg) * wv; wsum += wv;

            const float* bx = boxes + (size_t)((b * NF + f) * NQ + q) * 4;
            const float* tx = tbox + (size_t)(b * NF + f) * 4;
            bbox += fabsf(bx[0]-tx[0]) + fabsf(bx[1]-tx[1]) + fabsf(bx[2]-tx[2]) + fabsf(bx[3]-tx[3]);

            float sx0 = bx[0]-0.5f*bx[2], sy0 = bx[1]-0.5f*bx[3];
            float sx1 = bx[0]+0.5f*bx[2], sy1 = bx[1]+0.5f*bx[3];
            float tx0 = tx[0]-0.5f*tx[2], ty0 = tx[1]-0.5f*tx[3];
            float tx1 = tx[0]+0.5f*tx[2], ty1 = tx[1]+0.5f*tx[3];
            float a1 = (sx1-sx0)*(sy1-sy0);
            float a2 = (tx1-tx0)*(ty1-ty0);
            float iw = fmaxf(fminf(sx1,tx1) - fmaxf(sx0,tx0), 0.0f);
            float ih = fmaxf(fminf(sy1,ty1) - fmaxf(sy0,ty0), 0.0f);
            float inter = iw * ih;
            float uni = a1 + a2 - inter;
            float iou = inter / uni;
            float cw = fmaxf(fmaxf(sx1,tx1) - fminf(sx0,tx0), 0.0f);
            float ch = fmaxf(fmaxf(sy1,ty1) - fminf(sy0,ty0), 0.0f);
            float ac = cw * ch;
            giou += -(iou - (ac - uni) / ac);
        }
        C[b * NQ + q] = cls / wsum + bbox * (1.0f / NF) + giou * (1.0f / NF)
                      + cost_mask + cost_dice + cost_proj;
    }

    // ---- last block performs argmin + tail writes ----
    if (tid == 0) {
        __threadfence();
        unsigned v = atomicAdd(&g_done, 1u);
        isLast = (v == 2 * NQ - 1);
    }
    __syncthreads();
    if (!isLast) return;
    __threadfence();

    for (int bb = 0; bb < 2; ++bb) {
        float best = CUDART_INF_F; int bi = NQ;
        for (int qq = tid; qq < NQ; qq += 192) {
            float vv = C[bb * NQ + qq];
            if (vv < best || (vv == best && qq < bi)) { best = vv; bi = qq; }
        }
        #pragma unroll
        for (int o = 16; o; o >>= 1) {
            float ov = __shfl_down_sync(0xffffffff, best, o);
            int   oi = __shfl_down_sync(0xffffffff, bi,   o);
            if (ov < best || (ov == best && oi < bi)) { best = ov; bi = oi; }
        }
        __shared__ float sv[6]; __shared__ int si[6];
        if (lane == 0) { sv[warp] = best; si[warp] = bi; }
        __syncthreads();
        if (tid == 0) {
            for (int i = 1; i < 6; ++i) {
                if (sv[i] < best || (sv[i] == best && si[i] < bi)) { best = sv[i]; bi = si[i]; }
            }
            if (out_size >= 608) {
                long long* op = (long long*)(C + 600);
                op[bb] = (long long)bi;
                op[2 + bb] = 0ll;
                if (bb == 0) for (int i = 608; i < out_size; ++i) C[i] = 0.0f;
            } else if (out_size >= 604) {
                C[600 + bb] = (float)bi;
                C[602 + bb] = 0.0f;
                if (bb == 0) for (int i = 604; i < out_size; ++i) C[i] = 0.0f;
            } else {
                if (bb == 0) for (int i = 600; i < out_size; ++i) C[i] = 0.0f;
            }
        }
        __syncthreads();
    }
}

extern "C" void kernel_launch(void* const* d_in, const int* in_sizes, int n_in,
                              void* d_out, int out_size) {
    const float* logits = (const float*)d_in[0];
    const float* boxes  = (const float*)d_in[1];
    const float* masks  = (const float*)d_in[2];
    const float* tmask  = (const float*)d_in[3];
    const float* tbox   = (const float*)d_in[4];
    const int*   tvalid = (const int*)d_in[5];
    const unsigned char* vpad = (const unsigned char*)d_in[6];
    float* out = (float*)d_out;

    prep_kernel<<<192, 128>>>(tmask, vpad);
    cost_kernel<<<2 * NQ, 192>>>(logits, boxes, masks, tbox, tvalid, out, out_size);
}

// round 14
// speedup vs baseline: 1.2706x; 1.0965x over previous
#include <cuda_runtime.h>
#include <math_constants.h>

#define NF 8
#define NQ 300
#define HH 96
#define WW 96
#define HW (HH*WW)        // 9216
#define FHW (NF*HW)       // 73728
#define ALPHA_C 0.25f
#define EPSV 1e-8f
#define LN2F 0.69314718056f

// transposed meta: g_metaT[bf][c*96 + row] = {tmask bits, vpad bits}
__device__ __align__(16) uint2 g_metaT[16][3*HH];
__device__ unsigned g_done;

__device__ __forceinline__ float tanh_hw(float x) {
    float y; asm("tanh.approx.f32 %0, %1;" : "=f"(y) : "f"(x)); return y;
}
__device__ __forceinline__ float sigmoid_fast(float x) {
    float a = fabsf(x);
    float u = __expf(-a);
    float r = __fdividef(1.0f, 1.0f + u);
    return (x >= 0.0f) ? r : u * r;
}
__device__ __forceinline__ float warp_sum(float v) {
    #pragma unroll
    for (int o = 16; o; o >>= 1) v += __shfl_xor_sync(0xffffffff, v, o);
    return v;
}
__device__ __forceinline__ float warp_max(float v) {
    #pragma unroll
    for (int o = 16; o; o >>= 1) v = fmaxf(v, __shfl_xor_sync(0xffffffff, v, o));
    return v;
}

// ---------------------------------------------------------------------------
// Prep: ballots + counter reset. grid = 192 blocks, 128 threads.
// ---------------------------------------------------------------------------
__global__ __launch_bounds__(128) void prep_kernel(
    const float* __restrict__ tmask, const unsigned char* __restrict__ vpad)
{
    if (blockIdx.x == 0 && threadIdx.x == 0) g_done = 0u;
    int bf = blockIdx.x / 12;
    int rg = blockIdx.x % 12;
    int b = bf >> 3;
    int tid = threadIdx.x;
    int wp = tid >> 5, lane = tid & 31;
    const float* base = tmask + (size_t)bf * HW;
    const unsigned char* vb = vpad + (size_t)b * HW;

    #pragma unroll
    for (int rr = 0; rr < 2; ++rr) {
        int row = rg * 8 + wp * 2 + rr;
        const float* rp = base + row * WW;
        const unsigned char* vr = vb + row * WW;
        float v0 = rp[lane], v1 = rp[32 + lane], v2 = rp[64 + lane];
        unsigned char q0 = vr[lane], q1 = vr[32 + lane], q2 = vr[64 + lane];
        unsigned t0 = __ballot_sync(0xffffffff, v0 != 0.0f);
        unsigned t1 = __ballot_sync(0xffffffff, v1 != 0.0f);
        unsigned t2 = __ballot_sync(0xffffffff, v2 != 0.0f);
        unsigned p0 = __ballot_sync(0xffffffff, q0 != 0);
        unsigned p1 = __ballot_sync(0xffffffff, q1 != 0);
        unsigned p2 = __ballot_sync(0xffffffff, q2 != 0);
        if (lane == 0) {
            g_metaT[bf][0 * HH + row] = make_uint2(t0, p0);
            g_metaT[bf][1 * HH + row] = make_uint2(t1, p1);
            g_metaT[bf][2 * HH + row] = make_uint2(t2, p2);
        }
    }
}

// ---------------------------------------------------------------------------
// Cost: one block per (b,q). 192 threads = 6 warps; warp owns 16 rows/frame
// processed as 8 row-pairs; uint4 meta loads; warp-uniform vpad skip.
// ---------------------------------------------------------------------------
__global__ __launch_bounds__(192, 5) void cost_kernel(
    const float* __restrict__ logits,
    const float* __restrict__ boxes,
    const float* __restrict__ masks,
    const float* __restrict__ tbox,
    const int*   __restrict__ tvalid,
    float* __restrict__ C, int out_size)
{
    int blk = blockIdx.x;
    int b = blk / NQ, q = blk % NQ;
    int tid = threadIdx.x;
    int warp = tid >> 5, lane = tid & 31;
    unsigned bitm = 1u << lane;

    __shared__ float rowFinal[NF * HH];           // 3 KB
    __shared__ float colAll[NF * 3 * 192];        // 18 KB
    __shared__ unsigned orAll[NF * 3 * 6];
    __shared__ float red[6][10];
    __shared__ bool isLast;

    float facc = 0.0f, nacc = 0.0f, sacc = 0.0f;

    for (int f = 0; f < NF; ++f) {
        const float* mb = masks + (size_t)((b * NF + f) * NQ + q) * HW + lane;
        const uint2* mt = g_metaT[b * NF + f];
        float c0 = -CUDART_INF_F, c1 = -CUDART_INF_F, c2 = -CUDART_INF_F;
        unsigned o0 = 0u, o1 = 0u, o2 = 0u;
        #pragma unroll 2
        for (int pr = 0; pr < 8; ++pr) {
            int row = warp * 16 + pr * 2;
            uint4 mw0 = *reinterpret_cast<const uint4*>(&mt[0 * HH + row]);
            uint4 mw1 = *reinterpret_cast<const uint4*>(&mt[1 * HH + row]);
            uint4 mw2 = *reinterpret_cast<const uint4*>(&mt[2 * HH + row]);
            const float* rpa = mb + row * WW;
            const float* rpb = rpa + WW;
            float xa0 = rpa[0], xa1 = rpa[32], xa2 = rpa[64];
            float xb0 = rpb[0], xb1 = rpb[32], xb2 = rpb[64];
            // warp-uniform vpad skip (words identical across lanes)
            if (mw0.y | mw1.y | mw2.y | mw0.w | mw1.w | mw2.w) {
                if (mw0.y & bitm) xa0 = 0.0f;
                if (mw1.y & bitm) xa1 = 0.0f;
                if (mw2.y & bitm) xa2 = 0.0f;
                if (mw0.w & bitm) xb0 = 0.0f;
                if (mw1.w & bitm) xb1 = 0.0f;
                if (mw2.w & bitm) xb2 = 0.0f;
            }
            o0 |= mw0.x | mw0.z;
            o1 |= mw1.x | mw1.z;
            o2 |= mw2.x | mw2.z;

            #pragma unroll
            for (int c = 0; c < 3; ++c) {
                float xa = (c == 0) ? xa0 : (c == 1) ? xa1 : xa2;
                float xb = (c == 0) ? xb0 : (c == 1) ? xb1 : xb2;
                unsigned twa = (c == 0) ? mw0.x : (c == 1) ? mw1.x : mw2.x;
                unsigned twb = (c == 0) ? mw0.z : (c == 1) ? mw1.z : mw2.z;
                {
                    bool tb = (twa & bitm) != 0u;
                    float th = tanh_hw(0.5f * xa);
                    float lg2v = __log2f(1.0f + fabsf(th));
                    float xs = tb ? -xa : xa;
                    float m = fmaxf(xs, 0.0f);
                    float ce = fmaf(-LN2F, lg2v, m + LN2F);
                    float u = tb ? th : -th;
                    float omu = 1.0f - u;
                    float at4 = tb ? 0.0625f : 0.1875f;
                    facc = fmaf(ce * omu * omu, at4, facc);
                    sacc += th;
                    if (tb) nacc += th;
                }
                {
                    bool tb = (twb & bitm) != 0u;
                    float th = tanh_hw(0.5f * xb);
                    float lg2v = __log2f(1.0f + fabsf(th));
                    float xs = tb ? -xb : xb;
                    float m = fmaxf(xs, 0.0f);
                    float ce = fmaf(-LN2F, lg2v, m + LN2F);
                    float u = tb ? th : -th;
                    float omu = 1.0f - u;
                    float at4 = tb ? 0.0625f : 0.1875f;
                    facc = fmaf(ce * omu * omu, at4, facc);
                    sacc += th;
                    if (tb) nacc += th;
                }
            }
            c0 = fmaxf(c0, fmaxf(xa0, xb0));
            c1 = fmaxf(c1, fmaxf(xa1, xb1));
            c2 = fmaxf(c2, fmaxf(xa2, xb2));
            float rma = warp_max(fmaxf(fmaxf(xa0, xa1), xa2));
            float rmb = warp_max(fmaxf(fmaxf(xb0, xb1), xb2));
            if (lane == 0) {
                rowFinal[f * HH + row] = rma;
                rowFinal[f * HH + row + 1] = rmb;
            }
        }
        colAll[((f * 3 + 0) * 6 + warp) * 32 + lane] = c0;
        colAll[((f * 3 + 1) * 6 + warp) * 32 + lane] = c1;
        colAll[((f * 3 + 2) * 6 + warp) * 32 + lane] = c2;
        if (lane == 0) {
            orAll[(f * 3 + 0) * 6 + warp] = o0;
            orAll[(f * 3 + 1) * 6 + warp] = o1;
            orAll[(f * 3 + 2) * 6 + warp] = o2;
        }
    }
    __syncthreads();

    // projection partials + target stats from bits
    float sx = 0, nx = 0, sy = 0, ny = 0, tsum = 0, txs = 0, tys = 0;
    #pragma unroll
    for (int j = tid; j < NF * HH; j += 192) {
        int f = j / 96, jj = j % 96;
        const uint2* mt = g_metaT[b * NF + f];
        uint2 w0 = mt[0 * HH + jj], w1 = mt[1 * HH + jj], w2 = mt[2 * HH + jj];
        tsum += (float)(__popc(w0.x) + __popc(w1.x) + __popc(w2.x));
        float tgx = ((w0.x | w1.x | w2.x) != 0u) ? 1.0f : 0.0f;
        float px = sigmoid_fast(rowFinal[j]);
        sx += px; nx += px * tgx; txs += tgx;

        int cc = jj >> 5, l = jj & 31;
        const float* cp = &colAll[((f * 3 + cc) * 6) * 32 + l];
        const unsigned* op = &orAll[(f * 3 + cc) * 6];
        float m = cp[0];
        unsigned ow = op[0];
        #pragma unroll
        for (int wp = 1; wp < 6; ++wp) { m = fmaxf(m, cp[wp * 32]); ow |= op[wp]; }
        float tgy = ((ow >> l) & 1u) ? 1.0f : 0.0f;
        float py = sigmoid_fast(m);
        sy += py; ny += py * tgy; tys += tgy;
    }

    float v0 = warp_sum(facc), v1 = warp_sum(nacc), v2 = warp_sum(sacc);
    float v3 = warp_sum(sx),   v4 = warp_sum(nx);
    float v5 = warp_sum(sy),   v6 = warp_sum(ny);
    float v7 = warp_sum(tsum), v8 = warp_sum(txs), v9 = warp_sum(tys);
    if (lane == 0) {
        red[warp][0] = v0; red[warp][1] = v1; red[warp][2] = v2;
        red[warp][3] = v3; red[warp][4] = v4; red[warp][5] = v5; red[warp][6] = v6;
        red[warp][7] = v7; red[warp][8] = v8; red[warp][9] = v9;
    }
    __syncthreads();

    if (tid == 0) {
        float A[10];
        #pragma unroll
        for (int i = 0; i < 10; ++i) {
            float t = 0;
            #pragma unroll
            for (int w = 0; w < 6; ++w) t += red[w][i];
            A[i] = t;
        }
        float naccr = 0.5f * (A[7] + A[1]);       // sum_{t} p
        float saccr = 0.5f * ((float)FHW + A[2]); // sum p
        float cost_mask = A[0] / (float)FHW;
        float cost_dice = -((2.0f * naccr + 1.0f) / (saccr + A[7] + 1.0f));
        float dx = (2.0f * A[4] + 1.0f) / (A[3] + A[8] + 1.0f);
        float dy = (2.0f * A[6] + 1.0f) / (A[5] + A[9] + 1.0f);
        float cost_proj = -0.5f * (dy + dx);

        float cls = 0, wsum = 0, bbox = 0, giou = 0;
        #pragma unroll
        for (int f = 0; f < NF; ++f) {
            float lg = logits[(b * NF + f) * NQ + q];
            float p = sigmoid_fast(lg);
            float neg = (1.0f - ALPHA_C) * p * p * (-__logf(1.0f - p + EPSV));
            float pos = ALPHA_C * (1.0f - p) * (1.0f - p) * (-__logf(p + EPSV));
            float wv = (tvalid[b * NF + f] != 0) ? 1.0f : 0.0f;
            cls += (pos - neg) * wv; wsum += wv;

            const float* bx = boxes + (size_t)((b * NF + f) * NQ + q) * 4;
            const float* tx = tbox + (size_t)(b * NF + f) * 4;
            bbox += fabsf(bx[0]-tx[0]) + fabsf(bx[1]-tx[1]) + fabsf(bx[2]-tx[2]) + fabsf(bx[3]-tx[3]);

            float sx0 = bx[0]-0.5f*bx[2], sy0 = bx[1]-0.5f*bx[3];
            float sx1 = bx[0]+0.5f*bx[2], sy1 = bx[1]+0.5f*bx[3];
            float tx0 = tx[0]-0.5f*tx[2], ty0 = tx[1]-0.5f*tx[3];
            float tx1 = tx[0]+0.5f*tx[2], ty1 = tx[1]+0.5f*tx[3];
            float a1 = (sx1-sx0)*(sy1-sy0);
            float a2 = (tx1-tx0)*(ty1-ty0);
            float iw = fmaxf(fminf(sx1,tx1) - fmaxf(sx0,tx0), 0.0f);
            float ih = fmaxf(fminf(sy1,ty1) - fmaxf(sy0,ty0), 0.0f);
            float inter = iw * ih;
            float uni = a1 + a2 - inter;
            float iou = inter / uni;
            float cw = fmaxf(fmaxf(sx1,tx1) - fminf(sx0,tx0), 0.0f);
            float ch = fmaxf(fmaxf(sy1,ty1) - fminf(sy0,ty0), 0.0f);
            float ac = cw * ch;
            giou += -(iou - (ac - uni) / ac);
        }
        C[b * NQ + q] = cls / wsum + bbox * (1.0f / NF) + giou * (1.0f / NF)
                      + cost_mask + cost_dice + cost_proj;
    }

    // ---- last block performs argmin + tail writes ----
    if (tid == 0) {
        __threadfence();
        unsigned v = atomicAdd(&g_done, 1u);
        isLast = (v == 2 * NQ - 1);
    }
    __syncthreads();
    if (!isLast) return;
    __threadfence();

    for (int bb = 0; bb < 2; ++bb) {
        float best = CUDART_INF_F; int bi = NQ;
        for (int qq = tid; qq < NQ; qq += 192) {
            float vv = C[bb * NQ + qq];
            if (vv < best || (vv == best && qq < bi)) { best = vv; bi = qq; }
        }
        #pragma unroll
        for (int o = 16; o; o >>= 1) {
            float ov = __shfl_down_sync(0xffffffff, best, o);
            int   oi = __shfl_down_sync(0xffffffff, bi,   o);
            if (ov < best || (ov == best && oi < bi)) { best = ov; bi = oi; }
        }
        __shared__ float sv[6]; __shared__ int si[6];
        if (lane == 0) { sv[warp] = best; si[warp] = bi; }
        __syncthreads();
        if (tid == 0) {
            for (int i = 1; i < 6; ++i) {
                if (sv[i] < best || (sv[i] == best && si[i] < bi)) { best = sv[i]; bi = si[i]; }
            }
            if (out_size >= 608) {
                long long* op = (long long*)(C + 600);
                op[bb] = (long long)bi;
                op[2 + bb] = 0ll;
                if (bb == 0) for (int i = 608; i < out_size; ++i) C[i] = 0.0f;
            } else if (out_size >= 604) {
                C[600 + bb] = (float)bi;
                C[602 + bb] = 0.0f;
                if (bb == 0) for (int i = 604; i < out_size; ++i) C[i] = 0.0f;
            } else {
                if (bb == 0) for (int i = 600; i < out_size; ++i) C[i] = 0.0f;
            }
        }
        __syncthreads();
    }
}

extern "C" void kernel_launch(void* const* d_in, const int* in_sizes, int n_in,
                              void* d_out, int out_size) {
    const float* logits = (const float*)d_in[0];
    const float* boxes  = (const float*)d_in[1];
    const float* masks  = (const float*)d_in[2];
    const float* tmask  = (const float*)d_in[3];
    const float* tbox   = (const float*)d_in[4];
    const int*   tvalid = (const int*)d_in[5];
    const unsigned char* vpad = (const unsigned char*)d_in[6];
    float* out = (float*)d_out;

    prep_kernel<<<192, 128>>>(tmask, vpad);
    cost_kernel<<<2 * NQ, 192>>>(logits, boxes, masks, tbox, tvalid, out, out_size);
}